// round 11
// baseline (speedup 1.0000x reference)
#include <cuda_runtime.h>
#include <cuda_fp16.h>
#include <cstdint>

// x: [16384,1024] fp32 rows, groups of 16 tokens (G=1024 groups)
// ctrl[d*64+es], f1[d*4096+es*64+f], f2[es*65536+f*1024+d], bias[es*64+f]
// out[16384,1024] fp32, sum of 64 (e,s) contributions.

__device__ int    g_sel[1024 * 64];        // selected token per (group, es)
__device__ __half g_w1h[64 * 64 * 1024];   // [es][f][d] fp16
__device__ __half g_w2h[64 * 1024 * 64];   // [es][d][f] fp16
__device__ __half g_ch[64 * 1024];         // ctrl hi  [es][d]
__device__ __half g_cl[64 * 1024];         // ctrl lo  [es][d]
__device__ int    g_flag[65536];           // flagged (gid<<6)|es
__device__ int    g_nflag;

// ======================= helpers =======================
__device__ __forceinline__ uint32_t smem_u32(const void* p) {
    uint32_t a;
    asm("{ .reg .u64 t; cvta.to.shared.u64 t, %1; cvt.u32.u64 %0, t; }" : "=r"(a) : "l"(p));
    return a;
}
#define SWZ(b) ((b) ^ (((b) >> 3) & 0x70))

__device__ __forceinline__ void sts64(uint32_t a, uint32_t x, uint32_t y) {
    asm volatile("st.shared.v2.b32 [%0], {%1,%2};" :: "r"(a), "r"(x), "r"(y) : "memory");
}
__device__ __forceinline__ void sts128(uint32_t a, uint32_t x, uint32_t y, uint32_t z, uint32_t w) {
    asm volatile("st.shared.v4.b32 [%0], {%1,%2,%3,%4};" :: "r"(a), "r"(x), "r"(y), "r"(z), "r"(w) : "memory");
}
__device__ __forceinline__ void sts32(uint32_t a, uint32_t x) {
    asm volatile("st.shared.b32 [%0], %1;" :: "r"(a), "r"(x) : "memory");
}

#define LDSM4(r, addr) \
    asm volatile("ldmatrix.sync.aligned.m8n8.x4.shared.b16 {%0,%1,%2,%3}, [%4];" \
                 : "=r"((r)[0]), "=r"((r)[1]), "=r"((r)[2]), "=r"((r)[3]) : "r"(addr))

#define MMA16816(d, a, b0, b1) \
    asm volatile("mma.sync.aligned.m16n8k16.row.col.f32.f16.f16.f32 " \
                 "{%0,%1,%2,%3}, {%4,%5,%6,%7}, {%8,%9}, {%0,%1,%2,%3};" \
                 : "+f"((d)[0]), "+f"((d)[1]), "+f"((d)[2]), "+f"((d)[3]) \
                 : "r"((a)[0]), "r"((a)[1]), "r"((a)[2]), "r"((a)[3]), "r"(b0), "r"(b1))

__device__ __forceinline__ void red_v4(float* p, float4 v) {
    asm volatile("red.global.add.v4.f32 [%0], {%1,%2,%3,%4};"
                 :: "l"(p), "f"(v.x), "f"(v.y), "f"(v.z), "f"(v.w) : "memory");
}

__device__ __forceinline__ uint32_t pack_h2(float lo, float hi) {
    __half2 h = __floats2half2_rn(lo, hi);
    return *(uint32_t*)&h;
}

// ======================= kernel 0: zero out =======================
__global__ void k_zero(float4* __restrict__ out, int n4) {
    int i = blockIdx.x * blockDim.x + threadIdx.x;
    int stride = gridDim.x * blockDim.x;
    for (; i < n4; i += stride) out[i] = make_float4(0.f, 0.f, 0.f, 0.f);
}

// ======================= prep: fp16 weight transposes =======================
__global__ __launch_bounds__(256) void k_prep_w1(const float* __restrict__ f1) {
    __shared__ float t[32][33];
    int d0 = blockIdx.x * 32, es = blockIdx.y, f0 = blockIdx.z * 32;
    int tx = threadIdx.x & 31, ty = threadIdx.x >> 5;
#pragma unroll
    for (int p = 0; p < 4; p++)
        t[ty + p * 8][tx] = f1[(d0 + ty + p * 8) * 4096 + es * 64 + f0 + tx];
    __syncthreads();
#pragma unroll
    for (int p = 0; p < 4; p++) {
        int fl = ty + p * 8;
        g_w1h[es * 65536 + (f0 + fl) * 1024 + d0 + tx] = __float2half(t[tx][fl]);
    }
}

__global__ __launch_bounds__(256) void k_prep_w2(const float* __restrict__ f2) {
    __shared__ float t[32][33];
    int d0 = blockIdx.x * 32, es = blockIdx.y, f0 = blockIdx.z * 32;
    int tx = threadIdx.x & 31, ty = threadIdx.x >> 5;
#pragma unroll
    for (int p = 0; p < 4; p++)
        t[ty + p * 8][tx] = f2[es * 65536 + (f0 + ty + p * 8) * 1024 + d0 + tx];
    __syncthreads();
#pragma unroll
    for (int p = 0; p < 4; p++) {
        int dl = ty + p * 8;
        g_w2h[es * 65536 + (d0 + dl) * 64 + f0 + tx] = __float2half(t[tx][dl]);
    }
}

// ctrl [d][es] -> split fp16 transposed [es][d]; also reset flag counter
__global__ __launch_bounds__(256) void k_prep_c(const float* __restrict__ ctrl) {
    __shared__ float t[32][33];
    int d0 = blockIdx.x * 32, es0 = blockIdx.y * 32;
    int tx = threadIdx.x & 31, ty = threadIdx.x >> 5;
    if (blockIdx.x == 0 && blockIdx.y == 0 && threadIdx.x == 0) g_nflag = 0;
#pragma unroll
    for (int p = 0; p < 4; p++)
        t[ty + p * 8][tx] = ctrl[(d0 + ty + p * 8) * 64 + es0 + tx];
    __syncthreads();
#pragma unroll
    for (int p = 0; p < 4; p++) {
        int el = ty + p * 8;
        float v = t[tx][el];
        __half hi = __float2half(v);
        float lo = v - __half2float(hi);
        g_ch[(es0 + el) * 1024 + d0 + tx] = hi;
        g_cl[(es0 + el) * 1024 + d0 + tx] = __float2half(lo);
    }
}

// ======================= kernel 1: HMMA split-fp16 router =======================
// grid 128 (m-tiles of 128 token rows), 256 threads / 8 warps (4M x 2N).
// logits = x_hi*c_hi + x_lo*c_hi + x_hi*c_lo  (fp32 accum; |err| < ~2e-6)
// argmax over 16 tokens per (group, es); margin < 3e-5 -> flag for exact redo.
__global__ __launch_bounds__(256) void k_router_h(const float* __restrict__ x) {
    extern __shared__ char dsm[];
    const int tid = threadIdx.x;
    const int lane = tid & 31;
    const int wid = tid >> 5;
    const int mw = wid >> 1;
    const int nw = wid & 1;
    const int m0 = blockIdx.x * 128;

    const uint32_t smemu = smem_u32(dsm);
    const uint32_t base = (smemu + 1023) & ~1023u;
    const uint32_t Ahi = base;            // 16KB [128][64] fp16
    const uint32_t Alo = base + 16384;    // 16KB
    const uint32_t Bhi = base + 32768;    // 8KB  [64es][64k]
    const uint32_t Blo = base + 40960;    // 8KB
    float* Ls = (float*)(dsm + (base - smemu));  // overlay: [128][68] f32 logits

    const int r0 = tid >> 4;
    const int k4 = (tid & 15) << 2;
    const int fB = tid >> 3;          // es row 0..31 (q loop covers 64)
    const int k16 = (tid & 7) << 3;

    float acc[2][4][4];
#pragma unroll
    for (int mi = 0; mi < 2; mi++)
#pragma unroll
        for (int nj = 0; nj < 4; nj++)
#pragma unroll
            for (int e = 0; e < 4; e++) acc[mi][nj][e] = 0.f;

    float4 av[8];
    uint4 bvh[2], bvl[2];
#pragma unroll
    for (int q = 0; q < 8; q++)
        av[q] = *(const float4*)(x + (size_t)(m0 + q * 16 + r0) * 1024 + k4);
#pragma unroll
    for (int q = 0; q < 2; q++) {
        bvh[q] = *(const uint4*)(g_ch + (q * 32 + fB) * 1024 + k16);
        bvl[q] = *(const uint4*)(g_cl + (q * 32 + fB) * 1024 + k16);
    }

    for (int c = 0; c < 16; c++) {
        // stage A: hi = rn(x), lo = rn(x - hi); same fp32 source for both
#pragma unroll
        for (int q = 0; q < 8; q++) {
            float4 v = av[q];
            float hx = __half2float(__float2half(v.x));
            float hy = __half2float(__float2half(v.y));
            float hz = __half2float(__float2half(v.z));
            float hw = __half2float(__float2half(v.w));
            uint32_t byte = (q * 16 + r0) * 128 + (k4 << 1);
            sts64(Ahi + SWZ(byte), pack_h2(hx, hy), pack_h2(hz, hw));
            sts64(Alo + SWZ(byte), pack_h2(v.x - hx, v.y - hy), pack_h2(v.z - hz, v.w - hw));
        }
#pragma unroll
        for (int q = 0; q < 2; q++) {
            uint32_t byte = (q * 32 + fB) * 128 + (k16 << 1);
            sts128(Bhi + SWZ(byte), bvh[q].x, bvh[q].y, bvh[q].z, bvh[q].w);
            sts128(Blo + SWZ(byte), bvl[q].x, bvl[q].y, bvl[q].z, bvl[q].w);
        }
        __syncthreads();
        if (c < 15) {
            const int kc = (c + 1) * 64;
#pragma unroll
            for (int q = 0; q < 8; q++)
                av[q] = *(const float4*)(x + (size_t)(m0 + q * 16 + r0) * 1024 + kc + k4);
#pragma unroll
            for (int q = 0; q < 2; q++) {
                bvh[q] = *(const uint4*)(g_ch + (q * 32 + fB) * 1024 + kc + k16);
                bvl[q] = *(const uint4*)(g_cl + (q * 32 + fB) * 1024 + kc + k16);
            }
        }
#pragma unroll
        for (int ks = 0; ks < 4; ks++) {
            uint32_t ah[2][4], al[2][4], bh[2][4], bl[2][4];
#pragma unroll
            for (int mi = 0; mi < 2; mi++) {
                uint32_t byte = (mw * 32 + mi * 16 + (lane & 15)) * 128 + ks * 32 + ((lane >> 4) << 4);
                LDSM4(ah[mi], Ahi + SWZ(byte));
                LDSM4(al[mi], Alo + SWZ(byte));
            }
#pragma unroll
            for (int ni = 0; ni < 2; ni++) {
                uint32_t byte = (nw * 32 + ni * 16 + (lane & 15)) * 128 + ks * 32 + ((lane >> 4) << 4);
                LDSM4(bh[ni], Bhi + SWZ(byte));
                LDSM4(bl[ni], Blo + SWZ(byte));
            }
#pragma unroll
            for (int mi = 0; mi < 2; mi++)
#pragma unroll
                for (int nj = 0; nj < 4; nj++) {
                    MMA16816(acc[mi][nj], ah[mi], bh[nj >> 1][nj & 1], bh[nj >> 1][(nj & 1) + 2]);
                    MMA16816(acc[mi][nj], al[mi], bh[nj >> 1][nj & 1], bh[nj >> 1][(nj & 1) + 2]);
                    MMA16816(acc[mi][nj], ah[mi], bl[nj >> 1][nj & 1], bl[nj >> 1][(nj & 1) + 2]);
                }
        }
        __syncthreads();
    }

    // stage logits to smem (overlays A/B tiles — all reads done)
#pragma unroll
    for (int mi = 0; mi < 2; mi++) {
        const int rA = mw * 32 + mi * 16 + (lane >> 2);
#pragma unroll
        for (int nj = 0; nj < 4; nj++) {
            const int cb = nw * 32 + nj * 8 + ((lane & 3) << 1);
            *(float2*)(Ls + rA * 68 + cb) = make_float2(acc[mi][nj][0], acc[mi][nj][1]);
            *(float2*)(Ls + (rA + 8) * 68 + cb) = make_float2(acc[mi][nj][2], acc[mi][nj][3]);
        }
    }
    __syncthreads();

    // argmax over the 16 tokens of each (group, es); 512 tasks, 2 per thread
#pragma unroll
    for (int q = 0; q < 2; q++) {
        int task = q * 256 + tid;
        int g = task >> 6;
        int es = task & 63;
        float m1 = -3.4e38f, m2 = -3.4e38f;
        int bt = 0;
#pragma unroll
        for (int t = 0; t < 16; t++) {
            float v = Ls[(g * 16 + t) * 68 + es] + (float)((double)t * (1e-6 / 15.0));
            if (v >= m1) { m2 = m1; m1 = v; bt = t; }
            else if (v > m2) { m2 = v; }
        }
        int gid = blockIdx.x * 8 + g;
        g_sel[gid * 64 + es] = bt;
        if (m1 - m2 < 3e-5f) {
            int i = atomicAdd(&g_nflag, 1);
            g_flag[i] = (gid << 6) | es;
        }
    }
}

// exact fp32 redo for margin-flagged (group, es)
__global__ void k_router_fix(const float* __restrict__ x, const float* __restrict__ ctrl) {
    int n = g_nflag;
    int stride = gridDim.x * blockDim.x;
    for (int i = blockIdx.x * blockDim.x + threadIdx.x; i < n; i += stride) {
        int f = g_flag[i];
        int gid = f >> 6, es = f & 63;
        float best = -3.4e38f;
        int bt = 0;
        for (int t = 0; t < 16; t++) {
            const float* xr = x + (size_t)(gid * 16 + t) * 1024;
            float s = 0.f;
            for (int d = 0; d < 1024; d++) s = fmaf(xr[d], ctrl[d * 64 + es], s);
            s += (float)((double)t * (1e-6 / 15.0));
            if (s >= best) { best = s; bt = t; }
        }
        g_sel[gid * 64 + es] = bt;
    }
}

// ======================= kernel 2: HMMA fp16 FFN =======================
__global__ __launch_bounds__(256, 2) void k_ffn(const float* __restrict__ x,
                                                const float* __restrict__ bias,
                                                float* __restrict__ out) {
    extern __shared__ char dsm[];
    __shared__ int selrow[128];
    __shared__ float biasS[64];

    const int tid = threadIdx.x;
    const int lane = tid & 31;
    const int wid = tid >> 5;
    const int mw = wid >> 1;
    const int nw = wid & 1;
    const int es = blockIdx.y;
    const int g0 = blockIdx.x * 128;

    const uint32_t smemu = smem_u32(dsm);
    const uint32_t base = (smemu + 1023) & ~1023u;
    const uint32_t HsB = base;
    const uint32_t A1B = base + 16384;
    const uint32_t B1B = base + 49152;
    const uint32_t B2B = base + 16384;
    float* Zs = (float*)(dsm + (base - smemu) + 32768);

    if (tid < 128) { int t = g_sel[(g0 + tid) * 64 + es]; selrow[tid] = (g0 + tid) * 16 + t; }
    if (tid < 64) biasS[tid] = bias[es * 64 + tid];
    __syncthreads();

    const int r0 = tid >> 4;
    const int k4 = (tid & 15) << 2;
    const int fB = tid >> 3;
    const int k16 = (tid & 7) << 3;

    float acc1[2][4][4];
#pragma unroll
    for (int mi = 0; mi < 2; mi++)
#pragma unroll
        for (int nj = 0; nj < 4; nj++)
#pragma unroll
            for (int e = 0; e < 4; e++) acc1[mi][nj][e] = 0.f;

    float4 av[8];
    uint4 bv[2];
#pragma unroll
    for (int q = 0; q < 8; q++)
        av[q] = *(const float4*)(x + (size_t)selrow[q * 16 + r0] * 1024 + k4);
#pragma unroll
    for (int q = 0; q < 2; q++)
        bv[q] = *(const uint4*)(g_w1h + (size_t)es * 65536 + (q * 32 + fB) * 1024 + k16);

    for (int c = 0; c < 16; c++) {
        const int b = c & 1;
        const uint32_t aB = A1B + b * 16384;
        const uint32_t bB = B1B + b * 8192;
#pragma unroll
        for (int q = 0; q < 8; q++) {
            uint32_t byte = (q * 16 + r0) * 128 + (k4 << 1);
            sts64(aB + SWZ(byte), pack_h2(av[q].x, av[q].y), pack_h2(av[q].z, av[q].w));
        }
#pragma unroll
        for (int q = 0; q < 2; q++) {
            uint32_t byte = (q * 32 + fB) * 128 + (k16 << 1);
            sts128(bB + SWZ(byte), bv[q].x, bv[q].y, bv[q].z, bv[q].w);
        }
        __syncthreads();
        if (c < 15) {
            const int kc = (c + 1) * 64;
#pragma unroll
            for (int q = 0; q < 8; q++)
                av[q] = *(const float4*)(x + (size_t)selrow[q * 16 + r0] * 1024 + kc + k4);
#pragma unroll
            for (int q = 0; q < 2; q++)
                bv[q] = *(const uint4*)(g_w1h + (size_t)es * 65536 + (q * 32 + fB) * 1024 + kc + k16);
        }
#pragma unroll
        for (int ks = 0; ks < 4; ks++) {
            uint32_t af[2][4], bf[2][4];
#pragma unroll
            for (int mi = 0; mi < 2; mi++) {
                uint32_t byte = (mw * 32 + mi * 16 + (lane & 15)) * 128 + ks * 32 + ((lane >> 4) << 4);
                LDSM4(af[mi], aB + SWZ(byte));
            }
#pragma unroll
            for (int ni = 0; ni < 2; ni++) {
                uint32_t byte = (nw * 32 + ni * 16 + (lane & 15)) * 128 + ks * 32 + ((lane >> 4) << 4);
                LDSM4(bf[ni], bB + SWZ(byte));
            }
#pragma unroll
            for (int mi = 0; mi < 2; mi++)
#pragma unroll
                for (int nj = 0; nj < 4; nj++)
                    MMA16816(acc1[mi][nj], af[mi], bf[nj >> 1][nj & 1], bf[nj >> 1][(nj & 1) + 2]);
        }
    }

#pragma unroll
    for (int mi = 0; mi < 2; mi++) {
        const int rA = mw * 32 + mi * 16 + (lane >> 2);
#pragma unroll
        for (int nj = 0; nj < 4; nj++) {
            const int cb = nw * 32 + nj * 8 + ((lane & 3) << 1);
            float b0 = biasS[cb], b1 = biasS[cb + 1];
            uint32_t lo = pack_h2(fmaxf(acc1[mi][nj][0] + b0, 0.f), fmaxf(acc1[mi][nj][1] + b1, 0.f));
            uint32_t hi = pack_h2(fmaxf(acc1[mi][nj][2] + b0, 0.f), fmaxf(acc1[mi][nj][3] + b1, 0.f));
            sts32(HsB + SWZ((uint32_t)(rA * 128 + cb * 2)), lo);
            sts32(HsB + SWZ((uint32_t)((rA + 8) * 128 + cb * 2)), hi);
        }
    }
    __syncthreads();

    uint4 bv2[2];
#pragma unroll
    for (int q = 0; q < 2; q++)
        bv2[q] = *(const uint4*)(g_w2h + (size_t)es * 65536 + (size_t)(q * 32 + fB) * 64 + k16);

    for (int nc = 0; nc < 16; nc++) {
        const int b = nc & 1;
        const uint32_t bB = B2B + b * 8192;
#pragma unroll
        for (int q = 0; q < 2; q++) {
            uint32_t byte = (q * 32 + fB) * 128 + (k16 << 1);
            sts128(bB + SWZ(byte), bv2[q].x, bv2[q].y, bv2[q].z, bv2[q].w);
        }
        __syncthreads();
        if (nc < 15) {
#pragma unroll
            for (int q = 0; q < 2; q++)
                bv2[q] = *(const uint4*)(g_w2h + (size_t)es * 65536 +
                                         (size_t)((nc + 1) * 64 + q * 32 + fB) * 64 + k16);
        }

        float acc2[2][4][4];
#pragma unroll
        for (int mi = 0; mi < 2; mi++)
#pragma unroll
            for (int nj = 0; nj < 4; nj++)
#pragma unroll
                for (int e = 0; e < 4; e++) acc2[mi][nj][e] = 0.f;

#pragma unroll
        for (int ks = 0; ks < 4; ks++) {
            uint32_t af[2][4], bf[2][4];
#pragma unroll
            for (int mi = 0; mi < 2; mi++) {
                uint32_t byte = (mw * 32 + mi * 16 + (lane & 15)) * 128 + ks * 32 + ((lane >> 4) << 4);
                LDSM4(af[mi], HsB + SWZ(byte));
            }
#pragma unroll
            for (int ni = 0; ni < 2; ni++) {
                uint32_t byte = (nw * 32 + ni * 16 + (lane & 15)) * 128 + ks * 32 + ((lane >> 4) << 4);
                LDSM4(bf[ni], bB + SWZ(byte));
            }
#pragma unroll
            for (int mi = 0; mi < 2; mi++)
#pragma unroll
                for (int nj = 0; nj < 4; nj++)
                    MMA16816(acc2[mi][nj], af[mi], bf[nj >> 1][nj & 1], bf[nj >> 1][(nj & 1) + 2]);
        }

#pragma unroll
        for (int mi = 0; mi < 2; mi++) {
            const int rA = mw * 32 + mi * 16 + (lane >> 2);
#pragma unroll
            for (int nj = 0; nj < 4; nj++) {
                const int cb = nw * 32 + nj * 8 + ((lane & 3) << 1);
                *(float2*)(Zs + rA * 68 + cb) = make_float2(acc2[mi][nj][0], acc2[mi][nj][1]);
                *(float2*)(Zs + (rA + 8) * 68 + cb) = make_float2(acc2[mi][nj][2], acc2[mi][nj][3]);
            }
        }
        __syncthreads();
#pragma unroll
        for (int q = 0; q < 8; q++) {
            int s = q * 256 + tid;
            int row = s >> 4;
            int c4 = (s & 15) << 2;
            float4 v = *(const float4*)(Zs + row * 68 + c4);
            red_v4(out + (size_t)selrow[row] * 1024 + nc * 64 + c4, v);
        }
        __syncthreads();
    }
}

// ======================= launch =======================
extern "C" void kernel_launch(void* const* d_in, const int* in_sizes, int n_in,
                              void* d_out, int out_size) {
    const float* x    = (const float*)d_in[0];
    const float* ctrl = (const float*)d_in[1];
    const float* f1   = (const float*)d_in[2];
    const float* f2   = (const float*)d_in[3];
    const float* bias = (const float*)d_in[4];
    float* out = (float*)d_out;

    cudaFuncSetAttribute(k_ffn, cudaFuncAttributeMaxDynamicSharedMemorySize, 69632);
    cudaFuncSetAttribute(k_router_h, cudaFuncAttributeMaxDynamicSharedMemorySize, 50176);

    k_zero<<<2048, 256>>>((float4*)out, out_size / 4);
    k_prep_c<<<dim3(32, 2), 256>>>(ctrl);
    k_prep_w1<<<dim3(32, 64, 2), 256>>>(f1);
    k_prep_w2<<<dim3(32, 64, 2), 256>>>(f2);
    k_router_h<<<128, 256, 50176>>>(x);
    k_router_fix<<<32, 128>>>(x, ctrl);
    k_ffn<<<dim3(8, 64), 256, 69632>>>(x, bias, out);
}

// round 15
// speedup vs baseline: 2.5724x; 2.5724x over previous
#include <cuda_runtime.h>
#include <cuda_fp16.h>
#include <cstdint>

// x: [16384,1024] fp32 rows, groups of 16 tokens (G=1024 groups)
// ctrl[d*64+es], f1[d*4096+es*64+f], f2[es*65536+f*1024+d], bias[es*64+f]
// out[16384,1024] fp32, sum of 64 (e,s) contributions.

__device__ int    g_sel[1024 * 64];        // selected token per (group, es)
__device__ __half g_w1h[64 * 64 * 1024];   // [es][f][d] fp16
__device__ __half g_w2h[64 * 1024 * 64];   // [es][d][f] fp16
__device__ __half g_ch[64 * 1024];         // ctrl hi  [es][d]
__device__ __half g_cl[64 * 1024];         // ctrl lo  [es][d]
__device__ int    g_flag[65536];           // flagged (gid<<6)|es
__device__ int    g_nflag;

// ======================= helpers =======================
__device__ __forceinline__ uint32_t smem_u32(const void* p) {
    uint32_t a;
    asm("{ .reg .u64 t; cvta.to.shared.u64 t, %1; cvt.u32.u64 %0, t; }" : "=r"(a) : "l"(p));
    return a;
}
#define SWZ(b) ((b) ^ (((b) >> 3) & 0x70))

__device__ __forceinline__ void sts64(uint32_t a, uint32_t x, uint32_t y) {
    asm volatile("st.shared.v2.b32 [%0], {%1,%2};" :: "r"(a), "r"(x), "r"(y) : "memory");
}
__device__ __forceinline__ void sts128(uint32_t a, uint32_t x, uint32_t y, uint32_t z, uint32_t w) {
    asm volatile("st.shared.v4.b32 [%0], {%1,%2,%3,%4};" :: "r"(a), "r"(x), "r"(y), "r"(z), "r"(w) : "memory");
}
__device__ __forceinline__ void sts32(uint32_t a, uint32_t x) {
    asm volatile("st.shared.b32 [%0], %1;" :: "r"(a), "r"(x) : "memory");
}

#define LDSM4(r, addr) \
    asm volatile("ldmatrix.sync.aligned.m8n8.x4.shared.b16 {%0,%1,%2,%3}, [%4];" \
                 : "=r"((r)[0]), "=r"((r)[1]), "=r"((r)[2]), "=r"((r)[3]) : "r"(addr))

#define MMA16816(d, a, b0, b1) \
    asm volatile("mma.sync.aligned.m16n8k16.row.col.f32.f16.f16.f32 " \
                 "{%0,%1,%2,%3}, {%4,%5,%6,%7}, {%8,%9}, {%0,%1,%2,%3};" \
                 : "+f"((d)[0]), "+f"((d)[1]), "+f"((d)[2]), "+f"((d)[3]) \
                 : "r"((a)[0]), "r"((a)[1]), "r"((a)[2]), "r"((a)[3]), "r"(b0), "r"(b1))

__device__ __forceinline__ void red_v4(float* p, float4 v) {
    asm volatile("red.global.add.v4.f32 [%0], {%1,%2,%3,%4};"
                 :: "l"(p), "f"(v.x), "f"(v.y), "f"(v.z), "f"(v.w) : "memory");
}

__device__ __forceinline__ uint32_t pack_h2(float lo, float hi) {
    __half2 h = __floats2half2_rn(lo, hi);
    return *(uint32_t*)&h;
}

// ======================= kernel 0: zero out =======================
__global__ void k_zero(float4* __restrict__ out, int n4) {
    int i = blockIdx.x * blockDim.x + threadIdx.x;
    int stride = gridDim.x * blockDim.x;
    for (; i < n4; i += stride) out[i] = make_float4(0.f, 0.f, 0.f, 0.f);
}

// ======================= prep: fp16 weight transposes =======================
__global__ __launch_bounds__(256) void k_prep_w1(const float* __restrict__ f1) {
    __shared__ float t[32][33];
    int d0 = blockIdx.x * 32, es = blockIdx.y, f0 = blockIdx.z * 32;
    int tx = threadIdx.x & 31, ty = threadIdx.x >> 5;
#pragma unroll
    for (int p = 0; p < 4; p++)
        t[ty + p * 8][tx] = f1[(d0 + ty + p * 8) * 4096 + es * 64 + f0 + tx];
    __syncthreads();
#pragma unroll
    for (int p = 0; p < 4; p++) {
        int fl = ty + p * 8;
        g_w1h[es * 65536 + (f0 + fl) * 1024 + d0 + tx] = __float2half(t[tx][fl]);
    }
}

__global__ __launch_bounds__(256) void k_prep_w2(const float* __restrict__ f2) {
    __shared__ float t[32][33];
    int d0 = blockIdx.x * 32, es = blockIdx.y, f0 = blockIdx.z * 32;
    int tx = threadIdx.x & 31, ty = threadIdx.x >> 5;
#pragma unroll
    for (int p = 0; p < 4; p++)
        t[ty + p * 8][tx] = f2[es * 65536 + (f0 + ty + p * 8) * 1024 + d0 + tx];
    __syncthreads();
#pragma unroll
    for (int p = 0; p < 4; p++) {
        int dl = ty + p * 8;
        g_w2h[es * 65536 + (d0 + dl) * 64 + f0 + tx] = __float2half(t[tx][dl]);
    }
}

// ctrl [d][es] -> split fp16 transposed [es][d]; also reset flag counter
__global__ __launch_bounds__(256) void k_prep_c(const float* __restrict__ ctrl) {
    __shared__ float t[32][33];
    int d0 = blockIdx.x * 32, es0 = blockIdx.y * 32;
    int tx = threadIdx.x & 31, ty = threadIdx.x >> 5;
    if (blockIdx.x == 0 && blockIdx.y == 0 && threadIdx.x == 0) g_nflag = 0;
#pragma unroll
    for (int p = 0; p < 4; p++)
        t[ty + p * 8][tx] = ctrl[(d0 + ty + p * 8) * 64 + es0 + tx];
    __syncthreads();
#pragma unroll
    for (int p = 0; p < 4; p++) {
        int el = ty + p * 8;
        float v = t[tx][el];
        __half hi = __float2half(v);
        float lo = v - __half2float(hi);
        g_ch[(es0 + el) * 1024 + d0 + tx] = hi;
        g_cl[(es0 + el) * 1024 + d0 + tx] = __float2half(lo);
    }
}

// ======================= kernel 1: HMMA split-fp16 router =======================
// grid 128 (m-tiles of 128 token rows), 256 threads / 8 warps (4M x 2N).
// logits = x_hi*c_hi + x_lo*c_hi + x_hi*c_lo  (fp32 accum; |err| < ~2e-6)
// argmax over 16 tokens per (group, es); margin < 3e-5 -> flag for exact redo.
__global__ __launch_bounds__(256) void k_router_h(const float* __restrict__ x) {
    extern __shared__ char dsm[];
    const int tid = threadIdx.x;
    const int lane = tid & 31;
    const int wid = tid >> 5;
    const int mw = wid >> 1;
    const int nw = wid & 1;
    const int m0 = blockIdx.x * 128;

    const uint32_t smemu = smem_u32(dsm);
    const uint32_t base = (smemu + 1023) & ~1023u;
    const uint32_t Ahi = base;            // 16KB [128][64] fp16
    const uint32_t Alo = base + 16384;    // 16KB
    const uint32_t Bhi = base + 32768;    // 8KB  [64es][64k]
    const uint32_t Blo = base + 40960;    // 8KB
    float* Ls = (float*)(dsm + (base - smemu));  // overlay: [128][68] f32 logits

    const int r0 = tid >> 4;
    const int k4 = (tid & 15) << 2;
    const int fB = tid >> 3;          // es row 0..31 (q loop covers 64)
    const int k16 = (tid & 7) << 3;

    float acc[2][4][4];
#pragma unroll
    for (int mi = 0; mi < 2; mi++)
#pragma unroll
        for (int nj = 0; nj < 4; nj++)
#pragma unroll
            for (int e = 0; e < 4; e++) acc[mi][nj][e] = 0.f;

    float4 av[8];
    uint4 bvh[2], bvl[2];
#pragma unroll
    for (int q = 0; q < 8; q++)
        av[q] = *(const float4*)(x + (size_t)(m0 + q * 16 + r0) * 1024 + k4);
#pragma unroll
    for (int q = 0; q < 2; q++) {
        bvh[q] = *(const uint4*)(g_ch + (q * 32 + fB) * 1024 + k16);
        bvl[q] = *(const uint4*)(g_cl + (q * 32 + fB) * 1024 + k16);
    }

    for (int c = 0; c < 16; c++) {
        // stage A: hi = rn(x), lo = rn(x - hi); same fp32 source for both
#pragma unroll
        for (int q = 0; q < 8; q++) {
            float4 v = av[q];
            float hx = __half2float(__float2half(v.x));
            float hy = __half2float(__float2half(v.y));
            float hz = __half2float(__float2half(v.z));
            float hw = __half2float(__float2half(v.w));
            uint32_t byte = (q * 16 + r0) * 128 + (k4 << 1);
            sts64(Ahi + SWZ(byte), pack_h2(hx, hy), pack_h2(hz, hw));
            sts64(Alo + SWZ(byte), pack_h2(v.x - hx, v.y - hy), pack_h2(v.z - hz, v.w - hw));
        }
#pragma unroll
        for (int q = 0; q < 2; q++) {
            uint32_t byte = (q * 32 + fB) * 128 + (k16 << 1);
            sts128(Bhi + SWZ(byte), bvh[q].x, bvh[q].y, bvh[q].z, bvh[q].w);
            sts128(Blo + SWZ(byte), bvl[q].x, bvl[q].y, bvl[q].z, bvl[q].w);
        }
        __syncthreads();
        if (c < 15) {
            const int kc = (c + 1) * 64;
#pragma unroll
            for (int q = 0; q < 8; q++)
                av[q] = *(const float4*)(x + (size_t)(m0 + q * 16 + r0) * 1024 + kc + k4);
#pragma unroll
            for (int q = 0; q < 2; q++) {
                bvh[q] = *(const uint4*)(g_ch + (q * 32 + fB) * 1024 + kc + k16);
                bvl[q] = *(const uint4*)(g_cl + (q * 32 + fB) * 1024 + kc + k16);
            }
        }
#pragma unroll
        for (int ks = 0; ks < 4; ks++) {
            uint32_t ah[2][4], al[2][4], bh[2][4], bl[2][4];
#pragma unroll
            for (int mi = 0; mi < 2; mi++) {
                uint32_t byte = (mw * 32 + mi * 16 + (lane & 15)) * 128 + ks * 32 + ((lane >> 4) << 4);
                LDSM4(ah[mi], Ahi + SWZ(byte));
                LDSM4(al[mi], Alo + SWZ(byte));
            }
#pragma unroll
            for (int ni = 0; ni < 2; ni++) {
                uint32_t byte = (nw * 32 + ni * 16 + (lane & 15)) * 128 + ks * 32 + ((lane >> 4) << 4);
                LDSM4(bh[ni], Bhi + SWZ(byte));
                LDSM4(bl[ni], Blo + SWZ(byte));
            }
#pragma unroll
            for (int mi = 0; mi < 2; mi++)
#pragma unroll
                for (int nj = 0; nj < 4; nj++) {
                    MMA16816(acc[mi][nj], ah[mi], bh[nj >> 1][nj & 1], bh[nj >> 1][(nj & 1) + 2]);
                    MMA16816(acc[mi][nj], al[mi], bh[nj >> 1][nj & 1], bh[nj >> 1][(nj & 1) + 2]);
                    MMA16816(acc[mi][nj], ah[mi], bl[nj >> 1][nj & 1], bl[nj >> 1][(nj & 1) + 2]);
                }
        }
        __syncthreads();
    }

    // stage logits to smem (overlays A/B tiles — all reads done)
#pragma unroll
    for (int mi = 0; mi < 2; mi++) {
        const int rA = mw * 32 + mi * 16 + (lane >> 2);
#pragma unroll
        for (int nj = 0; nj < 4; nj++) {
            const int cb = nw * 32 + nj * 8 + ((lane & 3) << 1);
            *(float2*)(Ls + rA * 68 + cb) = make_float2(acc[mi][nj][0], acc[mi][nj][1]);
            *(float2*)(Ls + (rA + 8) * 68 + cb) = make_float2(acc[mi][nj][2], acc[mi][nj][3]);
        }
    }
    __syncthreads();

    // argmax over the 16 tokens of each (group, es); 512 tasks, 2 per thread
#pragma unroll
    for (int q = 0; q < 2; q++) {
        int task = q * 256 + tid;
        int g = task >> 6;
        int es = task & 63;
        float m1 = -3.4e38f, m2 = -3.4e38f;
        int bt = 0;
#pragma unroll
        for (int t = 0; t < 16; t++) {
            float v = Ls[(g * 16 + t) * 68 + es] + (float)((double)t * (1e-6 / 15.0));
            if (v >= m1) { m2 = m1; m1 = v; bt = t; }
            else if (v > m2) { m2 = v; }
        }
        int gid = blockIdx.x * 8 + g;
        g_sel[gid * 64 + es] = bt;
        if (m1 - m2 < 3e-5f) {
            int i = atomicAdd(&g_nflag, 1);
            g_flag[i] = (gid << 6) | es;
        }
    }
}

// exact fp32 redo for margin-flagged (group, es): ONE WARP PER TASK.
// Lanes stride d (coalesced), shfl-reduce per token; lane 0 writes selection.
__global__ __launch_bounds__(256) void k_router_fix(const float* __restrict__ x,
                                                    const float* __restrict__ ctrl) {
    const int n = g_nflag;
    const int lane = threadIdx.x & 31;
    const int warp = (blockIdx.x * blockDim.x + threadIdx.x) >> 5;
    const int nwarps = (gridDim.x * blockDim.x) >> 5;
    for (int i = warp; i < n; i += nwarps) {
        int f = g_flag[i];
        int gid = f >> 6, es = f & 63;
        float best = -3.4e38f;
        int bt = 0;
        for (int t = 0; t < 16; t++) {
            const float* xr = x + (size_t)(gid * 16 + t) * 1024;
            float s = 0.f;
#pragma unroll 8
            for (int d = lane; d < 1024; d += 32)
                s = fmaf(xr[d], ctrl[d * 64 + es], s);
#pragma unroll
            for (int m = 16; m >= 1; m >>= 1)
                s += __shfl_xor_sync(0xffffffffu, s, m);
            s += (float)((double)t * (1e-6 / 15.0));
            if (s >= best) { best = s; bt = t; }
        }
        if (lane == 0) g_sel[gid * 64 + es] = bt;
    }
}

// ======================= kernel 2: HMMA fp16 FFN =======================
__global__ __launch_bounds__(256, 2) void k_ffn(const float* __restrict__ x,
                                                const float* __restrict__ bias,
                                                float* __restrict__ out) {
    extern __shared__ char dsm[];
    __shared__ int selrow[128];
    __shared__ float biasS[64];

    const int tid = threadIdx.x;
    const int lane = tid & 31;
    const int wid = tid >> 5;
    const int mw = wid >> 1;
    const int nw = wid & 1;
    const int es = blockIdx.y;
    const int g0 = blockIdx.x * 128;

    const uint32_t smemu = smem_u32(dsm);
    const uint32_t base = (smemu + 1023) & ~1023u;
    const uint32_t HsB = base;
    const uint32_t A1B = base + 16384;
    const uint32_t B1B = base + 49152;
    const uint32_t B2B = base + 16384;
    float* Zs = (float*)(dsm + (base - smemu) + 32768);

    if (tid < 128) { int t = g_sel[(g0 + tid) * 64 + es]; selrow[tid] = (g0 + tid) * 16 + t; }
    if (tid < 64) biasS[tid] = bias[es * 64 + tid];
    __syncthreads();

    const int r0 = tid >> 4;
    const int k4 = (tid & 15) << 2;
    const int fB = tid >> 3;
    const int k16 = (tid & 7) << 3;

    float acc1[2][4][4];
#pragma unroll
    for (int mi = 0; mi < 2; mi++)
#pragma unroll
        for (int nj = 0; nj < 4; nj++)
#pragma unroll
            for (int e = 0; e < 4; e++) acc1[mi][nj][e] = 0.f;

    float4 av[8];
    uint4 bv[2];
#pragma unroll
    for (int q = 0; q < 8; q++)
        av[q] = *(const float4*)(x + (size_t)selrow[q * 16 + r0] * 1024 + k4);
#pragma unroll
    for (int q = 0; q < 2; q++)
        bv[q] = *(const uint4*)(g_w1h + (size_t)es * 65536 + (q * 32 + fB) * 1024 + k16);

    for (int c = 0; c < 16; c++) {
        const int b = c & 1;
        const uint32_t aB = A1B + b * 16384;
        const uint32_t bB = B1B + b * 8192;
#pragma unroll
        for (int q = 0; q < 8; q++) {
            uint32_t byte = (q * 16 + r0) * 128 + (k4 << 1);
            sts64(aB + SWZ(byte), pack_h2(av[q].x, av[q].y), pack_h2(av[q].z, av[q].w));
        }
#pragma unroll
        for (int q = 0; q < 2; q++) {
            uint32_t byte = (q * 32 + fB) * 128 + (k16 << 1);
            sts128(bB + SWZ(byte), bv[q].x, bv[q].y, bv[q].z, bv[q].w);
        }
        __syncthreads();
        if (c < 15) {
            const int kc = (c + 1) * 64;
#pragma unroll
            for (int q = 0; q < 8; q++)
                av[q] = *(const float4*)(x + (size_t)selrow[q * 16 + r0] * 1024 + kc + k4);
#pragma unroll
            for (int q = 0; q < 2; q++)
                bv[q] = *(const uint4*)(g_w1h + (size_t)es * 65536 + (q * 32 + fB) * 1024 + kc + k16);
        }
#pragma unroll
        for (int ks = 0; ks < 4; ks++) {
            uint32_t af[2][4], bf[2][4];
#pragma unroll
            for (int mi = 0; mi < 2; mi++) {
                uint32_t byte = (mw * 32 + mi * 16 + (lane & 15)) * 128 + ks * 32 + ((lane >> 4) << 4);
                LDSM4(af[mi], aB + SWZ(byte));
            }
#pragma unroll
            for (int ni = 0; ni < 2; ni++) {
                uint32_t byte = (nw * 32 + ni * 16 + (lane & 15)) * 128 + ks * 32 + ((lane >> 4) << 4);
                LDSM4(bf[ni], bB + SWZ(byte));
            }
#pragma unroll
            for (int mi = 0; mi < 2; mi++)
#pragma unroll
                for (int nj = 0; nj < 4; nj++)
                    MMA16816(acc1[mi][nj], af[mi], bf[nj >> 1][nj & 1], bf[nj >> 1][(nj & 1) + 2]);
        }
    }

#pragma unroll
    for (int mi = 0; mi < 2; mi++) {
        const int rA = mw * 32 + mi * 16 + (lane >> 2);
#pragma unroll
        for (int nj = 0; nj < 4; nj++) {
            const int cb = nw * 32 + nj * 8 + ((lane & 3) << 1);
            float b0 = biasS[cb], b1 = biasS[cb + 1];
            uint32_t lo = pack_h2(fmaxf(acc1[mi][nj][0] + b0, 0.f), fmaxf(acc1[mi][nj][1] + b1, 0.f));
            uint32_t hi = pack_h2(fmaxf(acc1[mi][nj][2] + b0, 0.f), fmaxf(acc1[mi][nj][3] + b1, 0.f));
            sts32(HsB + SWZ((uint32_t)(rA * 128 + cb * 2)), lo);
            sts32(HsB + SWZ((uint32_t)((rA + 8) * 128 + cb * 2)), hi);
        }
    }
    __syncthreads();

    uint4 bv2[2];
#pragma unroll
    for (int q = 0; q < 2; q++)
        bv2[q] = *(const uint4*)(g_w2h + (size_t)es * 65536 + (size_t)(q * 32 + fB) * 64 + k16);

    for (int nc = 0; nc < 16; nc++) {
        const int b = nc & 1;
        const uint32_t bB = B2B + b * 8192;
#pragma unroll
        for (int q = 0; q < 2; q++) {
            uint32_t byte = (q * 32 + fB) * 128 + (k16 << 1);
            sts128(bB + SWZ(byte), bv2[q].x, bv2[q].y, bv2[q].z, bv2[q].w);
        }
        __syncthreads();
        if (nc < 15) {
#pragma unroll
            for (int q = 0; q < 2; q++)
                bv2[q] = *(const uint4*)(g_w2h + (size_t)es * 65536 +
                                         (size_t)((nc + 1) * 64 + q * 32 + fB) * 64 + k16);
        }

        float acc2[2][4][4];
#pragma unroll
        for (int mi = 0; mi < 2; mi++)
#pragma unroll
            for (int nj = 0; nj < 4; nj++)
#pragma unroll
                for (int e = 0; e < 4; e++) acc2[mi][nj][e] = 0.f;

#pragma unroll
        for (int ks = 0; ks < 4; ks++) {
            uint32_t af[2][4], bf[2][4];
#pragma unroll
            for (int mi = 0; mi < 2; mi++) {
                uint32_t byte = (mw * 32 + mi * 16 + (lane & 15)) * 128 + ks * 32 + ((lane >> 4) << 4);
                LDSM4(af[mi], HsB + SWZ(byte));
            }
#pragma unroll
            for (int ni = 0; ni < 2; ni++) {
                uint32_t byte = (nw * 32 + ni * 16 + (lane & 15)) * 128 + ks * 32 + ((lane >> 4) << 4);
                LDSM4(bf[ni], bB + SWZ(byte));
            }
#pragma unroll
            for (int mi = 0; mi < 2; mi++)
#pragma unroll
                for (int nj = 0; nj < 4; nj++)
                    MMA16816(acc2[mi][nj], af[mi], bf[nj >> 1][nj & 1], bf[nj >> 1][(nj & 1) + 2]);
        }

#pragma unroll
        for (int mi = 0; mi < 2; mi++) {
            const int rA = mw * 32 + mi * 16 + (lane >> 2);
#pragma unroll
            for (int nj = 0; nj < 4; nj++) {
                const int cb = nw * 32 + nj * 8 + ((lane & 3) << 1);
                *(float2*)(Zs + rA * 68 + cb) = make_float2(acc2[mi][nj][0], acc2[mi][nj][1]);
                *(float2*)(Zs + (rA + 8) * 68 + cb) = make_float2(acc2[mi][nj][2], acc2[mi][nj][3]);
            }
        }
        __syncthreads();
#pragma unroll
        for (int q = 0; q < 8; q++) {
            int s = q * 256 + tid;
            int row = s >> 4;
            int c4 = (s & 15) << 2;
            float4 v = *(const float4*)(Zs + row * 68 + c4);
            red_v4(out + (size_t)selrow[row] * 1024 + nc * 64 + c4, v);
        }
        __syncthreads();
    }
}

// ======================= launch =======================
extern "C" void kernel_launch(void* const* d_in, const int* in_sizes, int n_in,
                              void* d_out, int out_size) {
    const float* x    = (const float*)d_in[0];
    const float* ctrl = (const float*)d_in[1];
    const float* f1   = (const float*)d_in[2];
    const float* f2   = (const float*)d_in[3];
    const float* bias = (const float*)d_in[4];
    float* out = (float*)d_out;

    cudaFuncSetAttribute(k_ffn, cudaFuncAttributeMaxDynamicSharedMemorySize, 69632);
    cudaFuncSetAttribute(k_router_h, cudaFuncAttributeMaxDynamicSharedMemorySize, 50176);

    k_zero<<<2048, 256>>>((float4*)out, out_size / 4);
    k_prep_c<<<dim3(32, 2), 256>>>(ctrl);
    k_prep_w1<<<dim3(32, 64, 2), 256>>>(f1);
    k_prep_w2<<<dim3(32, 64, 2), 256>>>(f2);
    k_router_h<<<128, 256, 50176>>>(x);
    k_router_fix<<<64, 256>>>(x, ctrl);
    k_ffn<<<dim3(8, 64), 256, 69632>>>(x, bias, out);
}

// round 17
// speedup vs baseline: 3.5275x; 1.3713x over previous
#include <cuda_runtime.h>
#include <cuda_fp16.h>
#include <cstdint>

// x: [16384,1024] fp32 rows, groups of 16 tokens (G=1024 groups)
// ctrl[d*64+es], f1[d*4096+es*64+f], f2[es*65536+f*1024+d], bias[es*64+f]
// out[16384,1024] fp32, sum of 64 (e,s) contributions.

#define AP 70

__device__ int    g_sel[1024 * 64];        // selected token per (group, es)
__device__ __half g_w1h[64 * 64 * 1024];   // [es][f][d] fp16
__device__ __half g_w2h[64 * 1024 * 64];   // [es][d][f] fp16
__device__ float  g_part[16384 * 128];     // partial logits [row][half*64+es]

// ======================= helpers =======================
__device__ __forceinline__ uint32_t smem_u32(const void* p) {
    uint32_t a;
    asm("{ .reg .u64 t; cvta.to.shared.u64 t, %1; cvt.u32.u64 %0, t; }" : "=r"(a) : "l"(p));
    return a;
}
#define SWZ(b) ((b) ^ (((b) >> 3) & 0x70))

__device__ __forceinline__ void sts64(uint32_t a, uint32_t x, uint32_t y) {
    asm volatile("st.shared.v2.b32 [%0], {%1,%2};" :: "r"(a), "r"(x), "r"(y) : "memory");
}
__device__ __forceinline__ void sts128(uint32_t a, uint32_t x, uint32_t y, uint32_t z, uint32_t w) {
    asm volatile("st.shared.v4.b32 [%0], {%1,%2,%3,%4};" :: "r"(a), "r"(x), "r"(y), "r"(z), "r"(w) : "memory");
}
__device__ __forceinline__ void sts32(uint32_t a, uint32_t x) {
    asm volatile("st.shared.b32 [%0], %1;" :: "r"(a), "r"(x) : "memory");
}

#define LDSM4(r, addr) \
    asm volatile("ldmatrix.sync.aligned.m8n8.x4.shared.b16 {%0,%1,%2,%3}, [%4];" \
                 : "=r"((r)[0]), "=r"((r)[1]), "=r"((r)[2]), "=r"((r)[3]) : "r"(addr))

#define MMA16816(d, a, b0, b1) \
    asm volatile("mma.sync.aligned.m16n8k16.row.col.f32.f16.f16.f32 " \
                 "{%0,%1,%2,%3}, {%4,%5,%6,%7}, {%8,%9}, {%0,%1,%2,%3};" \
                 : "+f"((d)[0]), "+f"((d)[1]), "+f"((d)[2]), "+f"((d)[3]) \
                 : "r"((a)[0]), "r"((a)[1]), "r"((a)[2]), "r"((a)[3]), "r"(b0), "r"(b1))

__device__ __forceinline__ void red_v4(float* p, float4 v) {
    asm volatile("red.global.add.v4.f32 [%0], {%1,%2,%3,%4};"
                 :: "l"(p), "f"(v.x), "f"(v.y), "f"(v.z), "f"(v.w) : "memory");
}

__device__ __forceinline__ uint32_t pack_h2(float lo, float hi) {
    __half2 h = __floats2half2_rn(lo, hi);
    return *(uint32_t*)&h;
}

__device__ __forceinline__ unsigned long long ffma2(unsigned long long a, unsigned long long b, unsigned long long c) {
    unsigned long long d;
    asm("fma.rn.f32x2 %0, %1, %2, %3;" : "=l"(d) : "l"(a), "l"(b), "l"(c));
    return d;
}
__device__ __forceinline__ float2 unpack2(unsigned long long v) {
    float2 r; asm("mov.b64 {%0, %1}, %2;" : "=f"(r.x), "=f"(r.y) : "l"(v)); return r;
}

// ======================= kernel 0: zero out =======================
__global__ void k_zero(float4* __restrict__ out, int n4) {
    int i = blockIdx.x * blockDim.x + threadIdx.x;
    int stride = gridDim.x * blockDim.x;
    for (; i < n4; i += stride) out[i] = make_float4(0.f, 0.f, 0.f, 0.f);
}

// ======================= prep: fp16 weight transposes =======================
__global__ __launch_bounds__(256) void k_prep_w1(const float* __restrict__ f1) {
    __shared__ float t[32][33];
    int d0 = blockIdx.x * 32, es = blockIdx.y, f0 = blockIdx.z * 32;
    int tx = threadIdx.x & 31, ty = threadIdx.x >> 5;
#pragma unroll
    for (int p = 0; p < 4; p++)
        t[ty + p * 8][tx] = f1[(d0 + ty + p * 8) * 4096 + es * 64 + f0 + tx];
    __syncthreads();
#pragma unroll
    for (int p = 0; p < 4; p++) {
        int fl = ty + p * 8;
        g_w1h[es * 65536 + (f0 + fl) * 1024 + d0 + tx] = __float2half(t[tx][fl]);
    }
}

__global__ __launch_bounds__(256) void k_prep_w2(const float* __restrict__ f2) {
    __shared__ float t[32][33];
    int d0 = blockIdx.x * 32, es = blockIdx.y, f0 = blockIdx.z * 32;
    int tx = threadIdx.x & 31, ty = threadIdx.x >> 5;
#pragma unroll
    for (int p = 0; p < 4; p++)
        t[ty + p * 8][tx] = f2[es * 65536 + (f0 + ty + p * 8) * 1024 + d0 + tx];
    __syncthreads();
#pragma unroll
    for (int p = 0; p < 4; p++) {
        int dl = ty + p * 8;
        g_w2h[es * 65536 + (d0 + dl) * 64 + f0 + tx] = __float2half(t[tx][dl]);
    }
}

// ======================= kernel 1: fp32 router, 2-way K-split =======================
// grid (256, 2): block (bx,by) computes 64 rows x 64 es over K-half by.
// Writes fp32 partial logits to g_part[row][by*64+es] (coalesced via smem).
__global__ __launch_bounds__(256) void k_router_ks(const float* __restrict__ x,
                                                   const float* __restrict__ ctrl) {
    __shared__ __align__(16) float As[64 * AP];
    __shared__ __align__(16) float Bs[64 * AP];
    const int tid = threadIdx.x;
    const int rt = tid & 15;
    const int ct = tid >> 4;
    const int m0 = blockIdx.x * 64;
    const int kb = blockIdx.y * 512;

    unsigned long long acc[4][4];
#pragma unroll
    for (int i = 0; i < 4; i++)
#pragma unroll
        for (int j = 0; j < 4; j++) acc[i][j] = 0ull;

    for (int c = 0; c < 8; c++) {
        const int kc = kb + c * 64;
#pragma unroll
        for (int q = 0; q < 4; q++) {
            int id = tid + 256 * q;
            int r = id >> 4;
            int k4 = (id & 15) << 2;
            float4 v = *(const float4*)(x + (size_t)(m0 + r) * 1024 + kc + k4);
            float* dst = As + r * AP + k4;
            *(float2*)dst = make_float2(v.x, v.y);
            *(float2*)(dst + 2) = make_float2(v.z, v.w);
        }
#pragma unroll
        for (int q = 0; q < 4; q++) {
            int id = tid + 256 * q;
            int k = id >> 4;
            int e4 = (id & 15) << 2;
            float4 v = *(const float4*)(ctrl + (size_t)(kc + k) * 64 + e4);
            Bs[(e4 + 0) * AP + k] = v.x;
            Bs[(e4 + 1) * AP + k] = v.y;
            Bs[(e4 + 2) * AP + k] = v.z;
            Bs[(e4 + 3) * AP + k] = v.w;
        }
        __syncthreads();
#pragma unroll
        for (int k = 0; k < 64; k += 2) {
            unsigned long long a[4], b[4];
#pragma unroll
            for (int i = 0; i < 4; i++)
                a[i] = *(const unsigned long long*)(As + (rt + 16 * i) * AP + k);
#pragma unroll
            for (int j = 0; j < 4; j++)
                b[j] = *(const unsigned long long*)(Bs + (ct + 16 * j) * AP + k);
#pragma unroll
            for (int i = 0; i < 4; i++)
#pragma unroll
                for (int j = 0; j < 4; j++) acc[i][j] = ffma2(a[i], b[j], acc[i][j]);
        }
        __syncthreads();
    }

    // stage partial logits in smem (overlay As — all reads done), then coalesced store
    float* Ls = As;   // 64 x 68 fits inside 64*AP
#pragma unroll
    for (int i = 0; i < 4; i++)
#pragma unroll
        for (int j = 0; j < 4; j++) {
            float2 p = unpack2(acc[i][j]);
            Ls[(rt + 16 * i) * 68 + (ct + 16 * j)] = p.x + p.y;
        }
    __syncthreads();
#pragma unroll
    for (int q = 0; q < 16; q++) {
        int idx = q * 256 + tid;
        int r = idx >> 6;
        int e = idx & 63;
        g_part[(size_t)(m0 + r) * 128 + blockIdx.y * 64 + e] = Ls[r * 68 + e];
    }
}

// sum the two K-halves, argmax over 16 tokens per (group, es)
__global__ __launch_bounds__(256) void k_argmax() {
    int task = blockIdx.x * 1024 + threadIdx.x;
#pragma unroll
    for (int q = 0; q < 4; q++, task += 256) {
        int g = task >> 6;
        int es = task & 63;
        float m1 = -3.4e38f;
        int bt = 0;
#pragma unroll
        for (int t = 0; t < 16; t++) {
            const float* p = g_part + (size_t)(g * 16 + t) * 128 + es;
            float v = p[0] + p[64] + (float)((double)t * (1e-6 / 15.0));
            if (v >= m1) { m1 = v; bt = t; }
        }
        g_sel[g * 64 + es] = bt;
    }
}

// ======================= kernel 2: HMMA fp16 FFN =======================
__global__ __launch_bounds__(256, 2) void k_ffn(const float* __restrict__ x,
                                                const float* __restrict__ bias,
                                                float* __restrict__ out) {
    extern __shared__ char dsm[];
    __shared__ int selrow[128];
    __shared__ float biasS[64];

    const int tid = threadIdx.x;
    const int lane = tid & 31;
    const int wid = tid >> 5;
    const int mw = wid >> 1;
    const int nw = wid & 1;
    const int es = blockIdx.y;
    const int g0 = blockIdx.x * 128;

    const uint32_t smemu = smem_u32(dsm);
    const uint32_t base = (smemu + 1023) & ~1023u;
    const uint32_t HsB = base;
    const uint32_t A1B = base + 16384;
    const uint32_t B1B = base + 49152;
    const uint32_t B2B = base + 16384;
    float* Zs = (float*)(dsm + (base - smemu) + 32768);

    if (tid < 128) { int t = g_sel[(g0 + tid) * 64 + es]; selrow[tid] = (g0 + tid) * 16 + t; }
    if (tid < 64) biasS[tid] = bias[es * 64 + tid];
    __syncthreads();

    const int r0 = tid >> 4;
    const int k4 = (tid & 15) << 2;
    const int fB = tid >> 3;
    const int k16 = (tid & 7) << 3;

    float acc1[2][4][4];
#pragma unroll
    for (int mi = 0; mi < 2; mi++)
#pragma unroll
        for (int nj = 0; nj < 4; nj++)
#pragma unroll
            for (int e = 0; e < 4; e++) acc1[mi][nj][e] = 0.f;

    float4 av[8];
    uint4 bv[2];
#pragma unroll
    for (int q = 0; q < 8; q++)
        av[q] = *(const float4*)(x + (size_t)selrow[q * 16 + r0] * 1024 + k4);
#pragma unroll
    for (int q = 0; q < 2; q++)
        bv[q] = *(const uint4*)(g_w1h + (size_t)es * 65536 + (q * 32 + fB) * 1024 + k16);

    for (int c = 0; c < 16; c++) {
        const int b = c & 1;
        const uint32_t aB = A1B + b * 16384;
        const uint32_t bB = B1B + b * 8192;
#pragma unroll
        for (int q = 0; q < 8; q++) {
            uint32_t byte = (q * 16 + r0) * 128 + (k4 << 1);
            sts64(aB + SWZ(byte), pack_h2(av[q].x, av[q].y), pack_h2(av[q].z, av[q].w));
        }
#pragma unroll
        for (int q = 0; q < 2; q++) {
            uint32_t byte = (q * 32 + fB) * 128 + (k16 << 1);
            sts128(bB + SWZ(byte), bv[q].x, bv[q].y, bv[q].z, bv[q].w);
        }
        __syncthreads();
        if (c < 15) {
            const int kc = (c + 1) * 64;
#pragma unroll
            for (int q = 0; q < 8; q++)
                av[q] = *(const float4*)(x + (size_t)selrow[q * 16 + r0] * 1024 + kc + k4);
#pragma unroll
            for (int q = 0; q < 2; q++)
                bv[q] = *(const uint4*)(g_w1h + (size_t)es * 65536 + (q * 32 + fB) * 1024 + kc + k16);
        }
#pragma unroll
        for (int ks = 0; ks < 4; ks++) {
            uint32_t af[2][4], bf[2][4];
#pragma unroll
            for (int mi = 0; mi < 2; mi++) {
                uint32_t byte = (mw * 32 + mi * 16 + (lane & 15)) * 128 + ks * 32 + ((lane >> 4) << 4);
                LDSM4(af[mi], aB + SWZ(byte));
            }
#pragma unroll
            for (int ni = 0; ni < 2; ni++) {
                uint32_t byte = (nw * 32 + ni * 16 + (lane & 15)) * 128 + ks * 32 + ((lane >> 4) << 4);
                LDSM4(bf[ni], bB + SWZ(byte));
            }
#pragma unroll
            for (int mi = 0; mi < 2; mi++)
#pragma unroll
                for (int nj = 0; nj < 4; nj++)
                    MMA16816(acc1[mi][nj], af[mi], bf[nj >> 1][nj & 1], bf[nj >> 1][(nj & 1) + 2]);
        }
    }

#pragma unroll
    for (int mi = 0; mi < 2; mi++) {
        const int rA = mw * 32 + mi * 16 + (lane >> 2);
#pragma unroll
        for (int nj = 0; nj < 4; nj++) {
            const int cb = nw * 32 + nj * 8 + ((lane & 3) << 1);
            float b0 = biasS[cb], b1 = biasS[cb + 1];
            uint32_t lo = pack_h2(fmaxf(acc1[mi][nj][0] + b0, 0.f), fmaxf(acc1[mi][nj][1] + b1, 0.f));
            uint32_t hi = pack_h2(fmaxf(acc1[mi][nj][2] + b0, 0.f), fmaxf(acc1[mi][nj][3] + b1, 0.f));
            sts32(HsB + SWZ((uint32_t)(rA * 128 + cb * 2)), lo);
            sts32(HsB + SWZ((uint32_t)((rA + 8) * 128 + cb * 2)), hi);
        }
    }
    __syncthreads();

    uint4 bv2[2];
#pragma unroll
    for (int q = 0; q < 2; q++)
        bv2[q] = *(const uint4*)(g_w2h + (size_t)es * 65536 + (size_t)(q * 32 + fB) * 64 + k16);

    for (int nc = 0; nc < 16; nc++) {
        const int b = nc & 1;
        const uint32_t bB = B2B + b * 8192;
#pragma unroll
        for (int q = 0; q < 2; q++) {
            uint32_t byte = (q * 32 + fB) * 128 + (k16 << 1);
            sts128(bB + SWZ(byte), bv2[q].x, bv2[q].y, bv2[q].z, bv2[q].w);
        }
        __syncthreads();
        if (nc < 15) {
#pragma unroll
            for (int q = 0; q < 2; q++)
                bv2[q] = *(const uint4*)(g_w2h + (size_t)es * 65536 +
                                         (size_t)((nc + 1) * 64 + q * 32 + fB) * 64 + k16);
        }

        float acc2[2][4][4];
#pragma unroll
        for (int mi = 0; mi < 2; mi++)
#pragma unroll
            for (int nj = 0; nj < 4; nj++)
#pragma unroll
                for (int e = 0; e < 4; e++) acc2[mi][nj][e] = 0.f;

#pragma unroll
        for (int ks = 0; ks < 4; ks++) {
            uint32_t af[2][4], bf[2][4];
#pragma unroll
            for (int mi = 0; mi < 2; mi++) {
                uint32_t byte = (mw * 32 + mi * 16 + (lane & 15)) * 128 + ks * 32 + ((lane >> 4) << 4);
                LDSM4(af[mi], HsB + SWZ(byte));
            }
#pragma unroll
            for (int ni = 0; ni < 2; ni++) {
                uint32_t byte = (nw * 32 + ni * 16 + (lane & 15)) * 128 + ks * 32 + ((lane >> 4) << 4);
                LDSM4(bf[ni], bB + SWZ(byte));
            }
#pragma unroll
            for (int mi = 0; mi < 2; mi++)
#pragma unroll
                for (int nj = 0; nj < 4; nj++)
                    MMA16816(acc2[mi][nj], af[mi], bf[nj >> 1][nj & 1], bf[nj >> 1][(nj & 1) + 2]);
        }

#pragma unroll
        for (int mi = 0; mi < 2; mi++) {
            const int rA = mw * 32 + mi * 16 + (lane >> 2);
#pragma unroll
            for (int nj = 0; nj < 4; nj++) {
                const int cb = nw * 32 + nj * 8 + ((lane & 3) << 1);
                *(float2*)(Zs + rA * 68 + cb) = make_float2(acc2[mi][nj][0], acc2[mi][nj][1]);
                *(float2*)(Zs + (rA + 8) * 68 + cb) = make_float2(acc2[mi][nj][2], acc2[mi][nj][3]);
            }
        }
        __syncthreads();
#pragma unroll
        for (int q = 0; q < 8; q++) {
            int s = q * 256 + tid;
            int row = s >> 4;
            int c4 = (s & 15) << 2;
            float4 v = *(const float4*)(Zs + row * 68 + c4);
            red_v4(out + (size_t)selrow[row] * 1024 + nc * 64 + c4, v);
        }
        __syncthreads();
    }
}

// ======================= launch =======================
extern "C" void kernel_launch(void* const* d_in, const int* in_sizes, int n_in,
                              void* d_out, int out_size) {
    const float* x    = (const float*)d_in[0];
    const float* ctrl = (const float*)d_in[1];
    const float* f1   = (const float*)d_in[2];
    const float* f2   = (const float*)d_in[3];
    const float* bias = (const float*)d_in[4];
    float* out = (float*)d_out;

    cudaFuncSetAttribute(k_ffn, cudaFuncAttributeMaxDynamicSharedMemorySize, 69632);

    k_zero<<<2048, 256>>>((float4*)out, out_size / 4);
    k_prep_w1<<<dim3(32, 64, 2), 256>>>(f1);
    k_prep_w2<<<dim3(32, 64, 2), 256>>>(f2);
    k_router_ks<<<dim3(256, 2), 256>>>(x, ctrl);
    k_argmax<<<64, 256>>>();
    k_ffn<<<dim3(8, 64), 256, 69632>>>(x, bias, out);
}